// round 15
// baseline (speedup 1.0000x reference)
#include <cuda_runtime.h>
#include <cuda_fp16.h>

#define H 128
#define NT 512
#define ROWB 272          // bytes per padded fp16 row (136 elems) — conflict-free ldmatrix

typedef unsigned int u32;

#define MAXN_PAD 50176
#define MAXE 800768
__device__ __half g_node16[(size_t)MAXN_PAD * H]; // fp16 node_rep (L2-resident)
__device__ __half g_eh16[(size_t)MAXE * H];       // fp16 edge_h rows
__device__ u32    g_deg[MAXN_PAD];
__device__ u32    g_off[MAXN_PAD + 64];
__device__ u32    g_cur[MAXN_PAD];
__device__ u32    g_list[2 * MAXE];               // incidence lists (edge ids)
__device__ u32    g_tickets[2];

// ---------------------------------------------------------------------------
// helpers
// ---------------------------------------------------------------------------
__device__ __forceinline__ u32 pk_hf2(float lo, float hi_) {  // .h0=lo, .h1=hi
    u32 r; asm("cvt.rn.f16x2.f32 %0, %1, %2;" : "=r"(r) : "f"(hi_), "f"(lo)); return r;
}
__device__ __forceinline__ u32 hadd2(u32 a, u32 b) {
    u32 r; asm("add.rn.f16x2 %0, %1, %2;" : "=r"(r) : "r"(a), "r"(b)); return r;
}
__device__ __forceinline__ float2 h2f(u32 h) {
    __half2 hh = *reinterpret_cast<__half2*>(&h);
    return __half22float2(hh);
}
__device__ __forceinline__ u32 smem_u32(const void* p) {
    u32 a; asm("{ .reg .u64 t; cvta.to.shared.u64 t, %1; cvt.u32.u64 %0, t; }"
               : "=r"(a) : "l"(p)); return a;
}
__device__ __forceinline__ void bar_pair(int id) {
    asm volatile("bar.sync %0, 64;" :: "r"(id) : "memory");
}
__device__ __forceinline__ void ldsm_x4(u32* r, u32 addr) {
    asm volatile("ldmatrix.sync.aligned.m8n8.x4.shared.b16 {%0,%1,%2,%3}, [%4];"
                 : "=r"(r[0]), "=r"(r[1]), "=r"(r[2]), "=r"(r[3]) : "r"(addr));
}
__device__ __forceinline__ void ldsm_x4_t(u32* r, u32 addr) {
    asm volatile("ldmatrix.sync.aligned.m8n8.x4.trans.shared.b16 {%0,%1,%2,%3}, [%4];"
                 : "=r"(r[0]), "=r"(r[1]), "=r"(r[2]), "=r"(r[3]) : "r"(addr));
}
__device__ __forceinline__ void mma_f16(float* c, const u32* a, u32 b0, u32 b1) {
    asm volatile("mma.sync.aligned.m16n8k16.row.col.f32.f16.f16.f32 "
                 "{%0,%1,%2,%3}, {%4,%5,%6,%7}, {%8,%9}, {%0,%1,%2,%3};"
                 : "+f"(c[0]), "+f"(c[1]), "+f"(c[2]), "+f"(c[3])
                 : "r"(a[0]), "r"(a[1]), "r"(a[2]), "r"(a[3]), "r"(b0), "r"(b1));
}
__device__ __forceinline__ void st_h4(char* smc, int boff, float4 v) {
    *(uint2*)(smc + boff) = make_uint2(pk_hf2(v.x, v.y), pk_hf2(v.z, v.w));
}
__device__ __forceinline__ void load_w(char* smc, int off,
                                       const float* __restrict__ W, int tid) {
    for (int i = tid; i < H * (H / 4); i += NT) {
        int k = i >> 5, c4 = (i & 31) << 2;
        float4 v = __ldg((const float4*)&W[(size_t)k * H + c4]);
        st_h4(smc, off + k * ROWB + c4 * 2, v);
    }
}
__device__ __forceinline__ void zero16(float acc[16][4]) {
#pragma unroll
    for (int i = 0; i < 16; i++)
#pragma unroll
        for (int j = 0; j < 4; j++) acc[i][j] = 0.f;
}

// M=32 x N=64 per warp (paired): per ks 2 a-ldsm + 4 b-ldsm, 16 mma
template<int K0, int K1>
__device__ __forceinline__ void gemm32(u32 A, u32 B, float acc[16][4], int aa, int bb) {
#pragma unroll
    for (int ks = K0; ks < K1; ks++) {
        u32 a0[4], a1[4];
        ldsm_x4(a0, A + aa + ks * 32);
        ldsm_x4(a1, A + aa + 16 * ROWB + ks * 32);
#pragma unroll
        for (int tp = 0; tp < 4; tp++) {
            u32 b[4];
            ldsm_x4_t(b, B + bb + ks * (16 * ROWB) + tp * 32);
            mma_f16(acc[2 * tp],     a0, b[0], b[1]);
            mma_f16(acc[2 * tp + 1], a0, b[2], b[3]);
            mma_f16(acc[8 + 2 * tp],     a1, b[0], b[1]);
            mma_f16(acc[8 + 2 * tp + 1], a1, b[2], b[3]);
        }
    }
}

// M=16 x N=128 (node_out)
__device__ __forceinline__ void gemm16(u32 A, u32 B, float acc[16][4], int aa, int bb) {
#pragma unroll
    for (int ks = 0; ks < 8; ks++) {
        u32 a[4];
        ldsm_x4(a, A + aa + ks * 32);
#pragma unroll
        for (int tp = 0; tp < 8; tp++) {
            u32 b[4];
            ldsm_x4_t(b, B + bb + ks * (16 * ROWB) + tp * 32);
            mma_f16(acc[2 * tp],     a, b[0], b[1]);
            mma_f16(acc[2 * tp + 1], a, b[2], b[3]);
        }
    }
}

__device__ __forceinline__ float4 shuf_v4(const float c[4], int lane) {
    float t0 = __shfl_xor_sync(0xffffffffu, c[0], 1);
    float t1 = __shfl_xor_sync(0xffffffffu, c[1], 1);
    float t2 = __shfl_xor_sync(0xffffffffu, c[2], 1);
    float t3 = __shfl_xor_sync(0xffffffffu, c[3], 1);
    return (lane & 1) ? make_float4(t2, t3, c[2], c[3])
                      : make_float4(c[0], c[1], t0, t1);
}

// smem byte offsets
#define OFF_A   0
#define OFF_W1B 69632
#define OFF_W1T 104448
#define OFF_WL  139264
#define OFF_IDX 174080
#define OFF_PTK 176128
#define SMEM_EDGE 176192
#define SMEM_1W   104448

// ---------------------------------------------------------------------------
// K-zero: clear degree counters + tickets
// ---------------------------------------------------------------------------
extern "C" __global__ void k_zero() {
    int i = blockIdx.x * blockDim.x + threadIdx.x;
    if (i < MAXN_PAD / 4) ((uint4*)g_deg)[i] = make_uint4(0, 0, 0, 0);
    if (i == 0) { g_tickets[0] = 0; g_tickets[1] = 0; }
}

// ---------------------------------------------------------------------------
// K-prep: node16 = fp16(node) ; degree count (both endpoint halves of eidx)
// ---------------------------------------------------------------------------
extern "C" __global__ void __launch_bounds__(NT)
k_prep(const float* __restrict__ node, const int* __restrict__ eidx,
       int N, int E2)
{
    int i = blockIdx.x * NT + threadIdx.x;
    int totaln = N * (H / 4);
    if (i < totaln) {
        float4 v = __ldg((const float4*)node + i);
        ((uint2*)g_node16)[i] = make_uint2(pk_hf2(v.x, v.y), pk_hf2(v.z, v.w));
    }
    if (i < E2) {
        int n = __ldg(&eidx[i]);
        atomicAdd(&g_deg[n], 1u);
    }
}

// ---------------------------------------------------------------------------
// K-scan: exclusive prefix sum of degrees (single CTA)
// ---------------------------------------------------------------------------
extern "C" __global__ void __launch_bounds__(1024)
k_scan(int N)
{
    __shared__ u32 part[1024];
    const int t = threadIdx.x;
    const int chunk = (N + 1023) / 1024;
    const int s = t * chunk;
    const int e_ = min(s + chunk, N);
    u32 sum = 0;
    for (int i = s; i < e_; i++) sum += g_deg[i];
    part[t] = sum;
    __syncthreads();
    for (int off = 1; off < 1024; off <<= 1) {
        u32 v2 = (t >= off) ? part[t - off] : 0;
        __syncthreads();
        part[t] += v2;
        __syncthreads();
    }
    u32 run = part[t] - sum;     // exclusive prefix of this chunk
    for (int i = s; i < e_; i++) {
        u32 d = g_deg[i];
        g_off[i] = run;
        g_cur[i] = run;
        run += d;
    }
    if (e_ == N && s <= N) g_off[N] = part[1023];
}

// ---------------------------------------------------------------------------
// K-fill: scatter incidence lists (edge id per endpoint)
// ---------------------------------------------------------------------------
extern "C" __global__ void __launch_bounds__(NT)
k_fill(const int* __restrict__ eidx, int E, int E2)
{
    int i = blockIdx.x * NT + threadIdx.x;
    if (i >= E2) return;
    int n = __ldg(&eidx[i]);
    u32 pos = atomicAdd(&g_cur[n], 1u);
    g_list[pos] = (u32)(i < E ? i : i - E);
}

// ---------------------------------------------------------------------------
// K-edge: paired warps, 32-row tiles, NO atomics — edge_h written as fp16
//   nsum     = node16[src] + node16[dst]       (gather hidden under GEMM1a tail)
//   edge_h   = relu(edge_rep @ W1_bot + nsum @ W1_top)  -> g_eh16
//   edge_out = relu(((1+eps2)*edge_h + nsum) @ W_lift)
// ---------------------------------------------------------------------------
extern "C" __global__ void __launch_bounds__(NT, 1)
k_edge_mma(const float* __restrict__ edge_rep, const int* __restrict__ src,
           const int* __restrict__ dst, const float* __restrict__ W1,
           const float* __restrict__ Wl, const float* __restrict__ eps2p,
           float* __restrict__ edge_out, int E, int ntiles)
{
    extern __shared__ char smc[];
    const u32 smb = smem_u32(smc);
    const int tid = threadIdx.x, lane = tid & 31, wid = tid >> 5;
    const int pr = wid >> 1, ch = wid & 1;
    const int bar = pr + 1;
    const int prbase = pr * 32;
    int* sidx = (int*)(smc + OFF_IDX) + pr * 64;
    volatile int* ptk = (volatile int*)(smc + OFF_PTK) + pr;
    const float s2 = 1.f + __ldg(eps2p);

    load_w(smc, OFF_W1T, W1, tid);
    load_w(smc, OFF_W1B, W1 + (size_t)H * H, tid);
    load_w(smc, OFF_WL,  Wl, tid);
    __syncthreads();

    const int aa = (prbase + (lane & 15)) * ROWB + ((lane >> 4) << 4);
    const int bb = (lane & 15) * ROWB + ((lane >> 4) << 4) + ch * 128;
    const int rl = (lane >> 2) + ((lane & 1) << 3);
    const int q4 = ((lane >> 1) & 1) << 2;
    const int cc = ch * 64;
    const int myrow0 = OFF_A + (prbase + rl) * ROWB + cc * 2;
    const int myrow1 = myrow0 + 16 * ROWB;

    for (;;) {
        if (ch == 0 && lane == 0) *ptk = (int)atomicAdd(&g_tickets[0], 1u);
        bar_pair(bar);
        const int tk = *ptk;
        if (tk >= ntiles) break;
        const int base = tk * 32;

        {
            int e = base + lane; if (e >= E) e = E - 1;
            sidx[ch * 32 + lane] = ch ? __ldg(&dst[e]) : __ldg(&src[e]);
        }
#pragma unroll
        for (int i = 0; i < 16; i++) {
            int r = ch * 16 + i;
            int er = base + r; if (er >= E) er = E - 1;
            float4 v = __ldg((const float4*)&edge_rep[(size_t)er * H + lane * 4]);
            st_h4(smc, OFF_A + (prbase + r) * ROWB + lane * 8, v);
        }
        bar_pair(bar);

        float acc[16][4];
        zero16(acc);
        gemm32<0, 5>(smb + OFF_A, smb + OFF_W1B, acc, aa, bb);

        uint2 nsv[16];
#pragma unroll
        for (int i = 0; i < 16; i++) {
            int r = ch * 16 + i;
            int s = sidx[r], d = sidx[32 + r];
            uint2 vs = __ldg((const uint2*)((const char*)g_node16 + (size_t)s * 256 + lane * 8));
            uint2 vd = __ldg((const uint2*)((const char*)g_node16 + (size_t)d * 256 + lane * 8));
            nsv[i] = make_uint2(hadd2(vs.x, vd.x), hadd2(vs.y, vd.y));
        }

        gemm32<5, 8>(smb + OFF_A, smb + OFF_W1B, acc, aa, bb);
        bar_pair(bar);

#pragma unroll
        for (int i = 0; i < 16; i++)
            *(uint2*)(smc + OFF_A + (prbase + ch * 16 + i) * ROWB + lane * 8) = nsv[i];
        bar_pair(bar);

        gemm32<0, 8>(smb + OFF_A, smb + OFF_W1T, acc, aa, bb);

        // epilogue 1: h = relu(acc); write h16 row; A := (1+eps2)*h + nsum
#pragma unroll
        for (int m = 0; m < 2; m++) {
            const int r = m * 16 + rl;
            const int er = base + r;
            const bool valid = er < E;
            const int mr = m ? myrow1 : myrow0;
            __half* hp = &g_eh16[(size_t)er * H + cc];
#pragma unroll
            for (int j = 0; j < 8; j++) {
                float4 v = shuf_v4(acc[m * 8 + j], lane);
                const int cb = j * 8 + q4;
                float4 h;
                h.x = fmaxf(v.x, 0.f);
                h.y = fmaxf(v.y, 0.f);
                h.z = fmaxf(v.z, 0.f);
                h.w = fmaxf(v.w, 0.f);
                if (valid)
                    *(uint2*)(hp + cb) = make_uint2(pk_hf2(h.x, h.y), pk_hf2(h.z, h.w));
                uint2 ns = *(uint2*)(smc + mr + cb * 2);
                float2 n01 = h2f(ns.x), n23 = h2f(ns.y);
                float4 a2;
                a2.x = fmaf(s2, h.x, n01.x);
                a2.y = fmaf(s2, h.y, n01.y);
                a2.z = fmaf(s2, h.z, n23.x);
                a2.w = fmaf(s2, h.w, n23.y);
                st_h4(smc, mr + cb * 2, a2);
            }
        }
        bar_pair(bar);

        zero16(acc);
        gemm32<0, 8>(smb + OFF_A, smb + OFF_WL, acc, aa, bb);

#pragma unroll
        for (int m = 0; m < 2; m++) {
            const int r = m * 16 + rl;
            const int er = base + r;
            const bool valid = er < E;
            float* op = &edge_out[(size_t)er * H + cc];
#pragma unroll
            for (int j = 0; j < 8; j++) {
                float4 v = shuf_v4(acc[m * 8 + j], lane);
                const int cb = j * 8 + q4;
                float4 o = { fmaxf(v.x, 0.f), fmaxf(v.y, 0.f),
                             fmaxf(v.z, 0.f), fmaxf(v.w, 0.f) };
                if (valid) *(float4*)(op + cb) = o;
            }
        }
    }
}

// ---------------------------------------------------------------------------
// K-agg: node_out = relu(((1+eps1)*node + gather-sum(edge_h16)) @ W2)
// ---------------------------------------------------------------------------
extern "C" __global__ void __launch_bounds__(NT, 1)
k_agg(const float* __restrict__ node, const float* __restrict__ W2,
      const float* __restrict__ eps1p, float* __restrict__ node_out,
      int N, int ntiles)
{
    extern __shared__ char smc[];
    const u32 smb = smem_u32(smc);
    const int tid = threadIdx.x, lane = tid & 31, wid = tid >> 5;
    const int wr = wid * 16;
    const float s1 = 1.f + __ldg(eps1p);

    load_w(smc, OFF_W1B, W2, tid);
    __syncthreads();

    const int aa = (wr + (lane & 15)) * ROWB + ((lane >> 4) << 4);
    const int bb = (lane & 15) * ROWB + ((lane >> 4) << 4);
    const int rl = (lane >> 2) + ((lane & 1) << 3);
    const int q4 = ((lane >> 1) & 1) << 2;

    for (;;) {
        int tk;
        if (lane == 0) tk = (int)atomicAdd(&g_tickets[1], 1u);
        tk = __shfl_sync(0xffffffffu, tk, 0);
        if (tk >= ntiles) break;
        const int base = tk * 16;

#pragma unroll 1
        for (int i = 0; i < 16; i++) {
            int n = base + i;
            int nc = n < N ? n : N - 1;
            float4 a = __ldg((const float4*)&node[(size_t)nc * H + lane * 4]);
            a.x *= s1; a.y *= s1; a.z *= s1; a.w *= s1;
            u32 k0 = __ldg(&g_off[nc]);
            u32 k1 = __ldg(&g_off[nc + 1]);
            for (u32 k = k0; k < k1; k += 32) {
                int cnt = (int)min(32u, k1 - k);
                u32 el = (lane < cnt) ? __ldg(&g_list[k + lane]) : 0u;
                int j = 0;
                for (; j + 4 <= cnt; j += 4) {
                    u32 e0 = __shfl_sync(0xffffffffu, el, j);
                    u32 e1 = __shfl_sync(0xffffffffu, el, j + 1);
                    u32 e2 = __shfl_sync(0xffffffffu, el, j + 2);
                    u32 e3 = __shfl_sync(0xffffffffu, el, j + 3);
                    uint2 v0 = __ldg((const uint2*)&g_eh16[(size_t)e0 * H + lane * 4]);
                    uint2 v1 = __ldg((const uint2*)&g_eh16[(size_t)e1 * H + lane * 4]);
                    uint2 v2 = __ldg((const uint2*)&g_eh16[(size_t)e2 * H + lane * 4]);
                    uint2 v3 = __ldg((const uint2*)&g_eh16[(size_t)e3 * H + lane * 4]);
                    float2 f;
                    f = h2f(v0.x); a.x += f.x; a.y += f.y;
                    f = h2f(v0.y); a.z += f.x; a.w += f.y;
                    f = h2f(v1.x); a.x += f.x; a.y += f.y;
                    f = h2f(v1.y); a.z += f.x; a.w += f.y;
                    f = h2f(v2.x); a.x += f.x; a.y += f.y;
                    f = h2f(v2.y); a.z += f.x; a.w += f.y;
                    f = h2f(v3.x); a.x += f.x; a.y += f.y;
                    f = h2f(v3.y); a.z += f.x; a.w += f.y;
                }
                for (; j < cnt; j++) {
                    u32 e = __shfl_sync(0xffffffffu, el, j);
                    uint2 v = __ldg((const uint2*)&g_eh16[(size_t)e * H + lane * 4]);
                    float2 f0 = h2f(v.x), f1 = h2f(v.y);
                    a.x += f0.x; a.y += f0.y; a.z += f1.x; a.w += f1.y;
                }
            }
            st_h4(smc, OFF_A + (wr + i) * ROWB + lane * 8, a);
        }
        __syncwarp();

        const int row = base + rl;
        const bool valid = row < N;

        float acc[16][4];
        zero16(acc);
        gemm16(smb + OFF_A, smb + OFF_W1B, acc, aa, bb);
#pragma unroll
        for (int j = 0; j < 16; j++) {
            float4 v = shuf_v4(acc[j], lane);
            float4 o = { fmaxf(v.x, 0.f), fmaxf(v.y, 0.f),
                         fmaxf(v.z, 0.f), fmaxf(v.w, 0.f) };
            if (valid) *(float4*)&node_out[(size_t)row * H + j * 8 + q4] = o;
        }
        __syncwarp();
    }
}

// ---------------------------------------------------------------------------
extern "C" void kernel_launch(void* const* d_in, const int* in_sizes, int n_in,
                              void* d_out, int out_size) {
    const float* node = (const float*)d_in[0];
    const float* edge = (const float*)d_in[1];
    const int*   eidx = (const int*)d_in[2];
    const float* W1   = (const float*)d_in[3];
    const float* W2   = (const float*)d_in[4];
    const float* Wl   = (const float*)d_in[5];
    const float* e1   = (const float*)d_in[6];
    const float* e2   = (const float*)d_in[7];

    const int N = in_sizes[0] / H;
    const int E = in_sizes[1] / H;
    const int E2 = 2 * E;
    const int* src = eidx;
    const int* dst = eidx + E;

    float* out = (float*)d_out;
    float* node_out = out;                       // [N, H]
    float* edge_out = out + (size_t)N * H;       // [E, H]

    cudaFuncSetAttribute(k_edge_mma, cudaFuncAttributeMaxDynamicSharedMemorySize, SMEM_EDGE);
    cudaFuncSetAttribute(k_agg,      cudaFuncAttributeMaxDynamicSharedMemorySize, SMEM_1W);

    int nsm = 148;
    cudaDeviceGetAttribute(&nsm, cudaDevAttrMultiProcessorCount, 0);

    int tilesE = (E + 31) / 32;
    int tilesN = (N + 15) / 16;

    int prepBlocks = (((N * (H / 4)) > E2 ? (N * (H / 4)) : E2) + NT - 1) / NT;
    int fillBlocks = (E2 + NT - 1) / NT;

    k_zero<<<(MAXN_PAD / 4 + 511) / 512, 512>>>();
    k_prep<<<prepBlocks, NT>>>(node, eidx, N, E2);
    k_scan<<<1, 1024>>>(N);
    k_fill<<<fillBlocks, NT>>>(eidx, E, E2);
    k_edge_mma<<<nsm, NT, SMEM_EDGE>>>(edge, src, dst, W1, Wl, e2, edge_out, E, tilesE);
    k_agg<<<nsm, NT, SMEM_1W>>>(node, W2, e1, node_out, N, tilesN);
}

// round 16
// speedup vs baseline: 1.6435x; 1.6435x over previous
#include <cuda_runtime.h>
#include <cuda_fp16.h>

#define H 128
#define NT 512
#define ROWB 272          // bytes per padded fp16 row (136 elems) — conflict-free ldmatrix

typedef unsigned int u32;

#define MAXN_PAD 50176
__device__ float  g_acc[(size_t)MAXN_PAD * H];   // (1+eps1)*node_rep + scatter(edge_h)
__device__ __half g_node16[(size_t)MAXN_PAD * H];// fp16 copy of node_rep (L2-resident)
__device__ u32    g_tickets[2];                  // [0] edge tiles, [1] node_out tiles

// ---------------------------------------------------------------------------
// helpers
// ---------------------------------------------------------------------------
__device__ __forceinline__ u32 pk_hf2(float lo, float hi_) {  // .h0=lo, .h1=hi
    u32 r; asm("cvt.rn.f16x2.f32 %0, %1, %2;" : "=r"(r) : "f"(hi_), "f"(lo)); return r;
}
__device__ __forceinline__ u32 hadd2(u32 a, u32 b) {
    u32 r; asm("add.rn.f16x2 %0, %1, %2;" : "=r"(r) : "r"(a), "r"(b)); return r;
}
__device__ __forceinline__ float2 h2f(u32 h) {
    __half2 hh = *reinterpret_cast<__half2*>(&h);
    return __half22float2(hh);
}
__device__ __forceinline__ u32 smem_u32(const void* p) {
    u32 a; asm("{ .reg .u64 t; cvta.to.shared.u64 t, %1; cvt.u32.u64 %0, t; }"
               : "=r"(a) : "l"(p)); return a;
}
__device__ __forceinline__ void red_add_v4(float* p, float a, float b, float c, float d) {
    asm volatile("red.global.add.v4.f32 [%0], {%1,%2,%3,%4};"
                 :: "l"(p), "f"(a), "f"(b), "f"(c), "f"(d) : "memory");
}
__device__ __forceinline__ void bar_pair(int id) {
    asm volatile("bar.sync %0, 64;" :: "r"(id) : "memory");
}
__device__ __forceinline__ void ldsm_x4(u32* r, u32 addr) {
    asm volatile("ldmatrix.sync.aligned.m8n8.x4.shared.b16 {%0,%1,%2,%3}, [%4];"
                 : "=r"(r[0]), "=r"(r[1]), "=r"(r[2]), "=r"(r[3]) : "r"(addr));
}
__device__ __forceinline__ void ldsm_x4_t(u32* r, u32 addr) {
    asm volatile("ldmatrix.sync.aligned.m8n8.x4.trans.shared.b16 {%0,%1,%2,%3}, [%4];"
                 : "=r"(r[0]), "=r"(r[1]), "=r"(r[2]), "=r"(r[3]) : "r"(addr));
}
__device__ __forceinline__ void mma_f16(float* c, const u32* a, u32 b0, u32 b1) {
    asm volatile("mma.sync.aligned.m16n8k16.row.col.f32.f16.f16.f32 "
                 "{%0,%1,%2,%3}, {%4,%5,%6,%7}, {%8,%9}, {%0,%1,%2,%3};"
                 : "+f"(c[0]), "+f"(c[1]), "+f"(c[2]), "+f"(c[3])
                 : "r"(a[0]), "r"(a[1]), "r"(a[2]), "r"(a[3]), "r"(b0), "r"(b1));
}

// store fp32x4 -> fp16x4 (8B) at byte offset
__device__ __forceinline__ void st_h4(char* smc, int boff, float4 v) {
    *(uint2*)(smc + boff) = make_uint2(pk_hf2(v.x, v.y), pk_hf2(v.z, v.w));
}

// load 128x128 fp32 W (row-major [k][n]) -> fp16 smem tile
__device__ __forceinline__ void load_w(char* smc, int off,
                                       const float* __restrict__ W, int tid) {
    for (int i = tid; i < H * (H / 4); i += NT) {
        int k = i >> 5, c4 = (i & 31) << 2;
        float4 v = __ldg((const float4*)&W[(size_t)k * H + c4]);
        st_h4(smc, off + k * ROWB + c4 * 2, v);
    }
}

__device__ __forceinline__ void zero16(float acc[16][4]) {
#pragma unroll
    for (int i = 0; i < 16; i++)
#pragma unroll
        for (int j = 0; j < 4; j++) acc[i][j] = 0.f;
}

// M=32 x N=64 per warp (paired): per ks 2 a-ldsm + 4 b-ldsm, 16 mma
template<int K0, int K1>
__device__ __forceinline__ void gemm32(u32 A, u32 B, float acc[16][4], int aa, int bb) {
#pragma unroll
    for (int ks = K0; ks < K1; ks++) {
        u32 a0[4], a1[4];
        ldsm_x4(a0, A + aa + ks * 32);
        ldsm_x4(a1, A + aa + 16 * ROWB + ks * 32);
#pragma unroll
        for (int tp = 0; tp < 4; tp++) {
            u32 b[4];
            ldsm_x4_t(b, B + bb + ks * (16 * ROWB) + tp * 32);
            mma_f16(acc[2 * tp],     a0, b[0], b[1]);
            mma_f16(acc[2 * tp + 1], a0, b[2], b[3]);
            mma_f16(acc[8 + 2 * tp],     a1, b[0], b[1]);
            mma_f16(acc[8 + 2 * tp + 1], a1, b[2], b[3]);
        }
    }
}

// M=16 x N=128 (node_out): per ks 1 a-ldsm + 8 b-ldsm, 16 mma
__device__ __forceinline__ void gemm16(u32 A, u32 B, float acc[16][4], int aa, int bb) {
#pragma unroll
    for (int ks = 0; ks < 8; ks++) {
        u32 a[4];
        ldsm_x4(a, A + aa + ks * 32);
#pragma unroll
        for (int tp = 0; tp < 8; tp++) {
            u32 b[4];
            ldsm_x4_t(b, B + bb + ks * (16 * ROWB) + tp * 32);
            mma_f16(acc[2 * tp],     a, b[0], b[1]);
            mma_f16(acc[2 * tp + 1], a, b[2], b[3]);
        }
    }
}

// repack mma fragment quad -> contiguous float4 (even lane: row q; odd: row q+8)
__device__ __forceinline__ float4 shuf_v4(const float c[4], int lane) {
    float t0 = __shfl_xor_sync(0xffffffffu, c[0], 1);
    float t1 = __shfl_xor_sync(0xffffffffu, c[1], 1);
    float t2 = __shfl_xor_sync(0xffffffffu, c[2], 1);
    float t3 = __shfl_xor_sync(0xffffffffu, c[3], 1);
    return (lane & 1) ? make_float4(t2, t3, c[2], c[3])
                      : make_float4(c[0], c[1], t0, t1);
}

// smem byte offsets
#define OFF_A   0                 // A tile: 256 rows x 272B (8 pairs x 32 rows)
#define OFF_W1B 69632             // W1 bottom (edge_rep part)
#define OFF_W1T 104448            // W1 top (lift/nsum part)
#define OFF_WL  139264            // W_lift
#define OFF_IDX 174080            // 8 pairs x 64 ints (src|dst)
#define OFF_PTK 176128            // 8 pair-ticket ints
#define SMEM_EDGE 176192
#define SMEM_1W   104448          // node_out: A + one W

// ---------------------------------------------------------------------------
// K0: elementwise — g_acc = (1+eps1)*node ; node16 = fp16(node) ; ticket reset
// ---------------------------------------------------------------------------
extern "C" __global__ void __launch_bounds__(NT)
k_node_pre(const float* __restrict__ node, const float* __restrict__ eps1p, int N)
{
    if (blockIdx.x == 0 && threadIdx.x == 0) { g_tickets[0] = 0; g_tickets[1] = 0; }
    const float s1 = 1.f + __ldg(eps1p);
    int i = blockIdx.x * NT + threadIdx.x;
    int total = N * (H / 4);
    if (i >= total) return;
    float4 v = __ldg((const float4*)node + i);
    float4 o = { s1 * v.x, s1 * v.y, s1 * v.z, s1 * v.w };
    ((float4*)g_acc)[i] = o;
    ((uint2*)g_node16)[i] = make_uint2(pk_hf2(v.x, v.y), pk_hf2(v.z, v.w));
}

// ---------------------------------------------------------------------------
// K1: fused edge pipeline — paired warps, 32-row tiles, split-N (64 cols/warp)
//   nsum     = node16[src] + node16[dst]       (uint4 gather under GEMM1a tail)
//   edge_h   = relu(edge_rep @ W1_bot + nsum @ W1_top)
//   g_acc[src] += edge_h ; g_acc[dst] += edge_h          (red.v4)
//   edge_out = relu(((1+eps2)*edge_h + nsum) @ W_lift)   (fragment-direct STG)
// ---------------------------------------------------------------------------
extern "C" __global__ void __launch_bounds__(NT, 1)
k_edge_mma(const float* __restrict__ edge_rep, const int* __restrict__ src,
           const int* __restrict__ dst, const float* __restrict__ W1,
           const float* __restrict__ Wl, const float* __restrict__ eps2p,
           float* __restrict__ edge_out, int E, int ntiles)
{
    extern __shared__ char smc[];
    const u32 smb = smem_u32(smc);
    const int tid = threadIdx.x, lane = tid & 31, wid = tid >> 5;
    const int pr = wid >> 1, ch = wid & 1;       // pair id, warp-in-pair
    const int bar = pr + 1;                      // named barrier id 1..8
    const int prbase = pr * 32;                  // pair's rows in A tile
    int* sidx = (int*)(smc + OFF_IDX) + pr * 64; // [src 0..31 | dst 0..31]
    volatile int* ptk = (volatile int*)(smc + OFF_PTK) + pr;
    const float s2 = 1.f + __ldg(eps2p);

    load_w(smc, OFF_W1T, W1, tid);                    // W1 rows 0..127 (lift part)
    load_w(smc, OFF_W1B, W1 + (size_t)H * H, tid);    // W1 rows 128..255 (edge part)
    load_w(smc, OFF_WL,  Wl, tid);
    __syncthreads();

    const int aa = (prbase + (lane & 15)) * ROWB + ((lane >> 4) << 4);
    const int bb = (lane & 15) * ROWB + ((lane >> 4) << 4) + ch * 128;
    const int rl = (lane >> 2) + ((lane & 1) << 3);
    const int q4 = ((lane >> 1) & 1) << 2;
    const int cc = ch * 64;                      // this warp's column base
    const int myrow0 = OFF_A + (prbase + rl) * ROWB + cc * 2;
    const int myrow1 = myrow0 + 16 * ROWB;
    const int lh = lane >> 4;                    // 0/1 (row select for uint4 gather)
    const int lo16 = (lane & 15) * 16;           // byte offset within 256B row
    const int ra = lane >> 2;                    // fragment row 0..7
    const int csh = (lane & 3) * 2;              // fragment col shift

    for (;;) {
        // T1: pair ticket (w0 fetches; barrier also fences last iter's GEMM2 reads)
        if (ch == 0 && lane == 0) *ptk = (int)atomicAdd(&g_tickets[0], 1u);
        bar_pair(bar);
        const int tk = *ptk;
        if (tk >= ntiles) break;
        const int base = tk * 32;

        // indices: w0 loads src[0..31], w1 loads dst[0..31]
        {
            int e = base + lane; if (e >= E) e = E - 1;
            sidx[ch * 32 + lane] = ch ? __ldg(&dst[e]) : __ldg(&src[e]);
        }
        // A := edge rows (each warp loads its 16 of the pair's 32)
#pragma unroll
        for (int i = 0; i < 16; i++) {
            int r = ch * 16 + i;
            int er = base + r; if (er >= E) er = E - 1;
            float4 v = __ldg((const float4*)&edge_rep[(size_t)er * H + lane * 4]);
            st_h4(smc, OFF_A + (prbase + r) * ROWB + lane * 8, v);
        }
        bar_pair(bar);   // T2: A + idx ready

        // GEMM1a (ks 0..4): acc = edge_rep @ W1_bot
        float acc[16][4];
        zero16(acc);
        gemm32<0, 5>(smb + OFF_A, smb + OFF_W1B, acc, aa, bb);

        // nsum gather (uint4, 2 rows/iter) — overlaps GEMM1a tail
        uint4 nsv[8];
#pragma unroll
        for (int i = 0; i < 8; i++) {
            int r = ch * 16 + 2 * i + lh;
            int s = sidx[r], d = sidx[32 + r];
            uint4 vs = __ldg((const uint4*)((const char*)g_node16 + (size_t)s * 256 + lo16));
            uint4 vd = __ldg((const uint4*)((const char*)g_node16 + (size_t)d * 256 + lo16));
            nsv[i] = make_uint4(hadd2(vs.x, vd.x), hadd2(vs.y, vd.y),
                                hadd2(vs.z, vd.z), hadd2(vs.w, vd.w));
        }

        // GEMM1a (ks 5..8)
        gemm32<5, 8>(smb + OFF_A, smb + OFF_W1B, acc, aa, bb);
        bar_pair(bar);   // T3: both warps done reading edge A

        // A := nsum (STS.128)
#pragma unroll
        for (int i = 0; i < 8; i++) {
            int r = ch * 16 + 2 * i + lh;
            *(uint4*)(smc + OFF_A + (prbase + r) * ROWB + lo16) = nsv[i];
        }
        bar_pair(bar);   // T4: nsum ready

        // GEMM1b: acc += nsum @ W1_top
        gemm32<0, 8>(smb + OFF_A, smb + OFF_W1T, acc, aa, bb);

        // epilogue 1: h = relu(acc); scatter; A := (1+eps2)*h + nsum  (2 rows/thread)
#pragma unroll
        for (int m = 0; m < 2; m++) {
            const int r = m * 16 + rl;
            const int er = base + r;
            const bool valid = er < E;
            const int s = sidx[r], d = sidx[32 + r];
            float* As = &g_acc[(size_t)s * H + cc];
            float* Ad = &g_acc[(size_t)d * H + cc];
            const int mr = m ? myrow1 : myrow0;
#pragma unroll
            for (int j = 0; j < 8; j++) {
                float4 v = shuf_v4(acc[m * 8 + j], lane);
                const int cb = j * 8 + q4;
                float4 h;
                h.x = fmaxf(v.x, 0.f);
                h.y = fmaxf(v.y, 0.f);
                h.z = fmaxf(v.z, 0.f);
                h.w = fmaxf(v.w, 0.f);
                if (valid) {
                    red_add_v4(As + cb, h.x, h.y, h.z, h.w);
                    red_add_v4(Ad + cb, h.x, h.y, h.z, h.w);
                }
                uint2 ns = *(uint2*)(smc + mr + cb * 2);
                float2 n01 = h2f(ns.x), n23 = h2f(ns.y);
                float4 a2;
                a2.x = fmaf(s2, h.x, n01.x);
                a2.y = fmaf(s2, h.y, n01.y);
                a2.z = fmaf(s2, h.z, n23.x);
                a2.w = fmaf(s2, h.w, n23.y);
                st_h4(smc, mr + cb * 2, a2);
            }
        }
        bar_pair(bar);   // T5: A2 ready

        // GEMM2: acc = A2 @ W_lift
        zero16(acc);
        gemm32<0, 8>(smb + OFF_A, smb + OFF_WL, acc, aa, bb);

        // epilogue 2: relu, fragment-direct STG.64 (no shuffles)
#pragma unroll
        for (int m = 0; m < 2; m++) {
            const int er0 = base + m * 16 + ra;
            const int er1 = er0 + 8;
            const bool v0 = er0 < E, v1 = er1 < E;
#pragma unroll
            for (int j = 0; j < 8; j++) {
                const float* c = acc[m * 8 + j];
                const int col = cc + j * 8 + csh;
                float2 lo = { fmaxf(c[0], 0.f), fmaxf(c[1], 0.f) };
                float2 hi = { fmaxf(c[2], 0.f), fmaxf(c[3], 0.f) };
                if (v0) *(float2*)&edge_out[(size_t)er0 * H + col] = lo;
                if (v1) *(float2*)&edge_out[(size_t)er1 * H + col] = hi;
            }
        }
    }
}

// ---------------------------------------------------------------------------
// K2: node_out = relu(g_acc @ W2)  — per-warp ticket tiles, fragment STG
// ---------------------------------------------------------------------------
extern "C" __global__ void __launch_bounds__(NT, 1)
k_node_out(const float* __restrict__ W2, float* __restrict__ node_out,
           int N, int ntiles)
{
    extern __shared__ char smc[];
    const u32 smb = smem_u32(smc);
    const int tid = threadIdx.x, lane = tid & 31, wid = tid >> 5;
    const int wr = wid * 16;

    load_w(smc, OFF_W1B, W2, tid);
    __syncthreads();

    const int aa = (wr + (lane & 15)) * ROWB + ((lane >> 4) << 4);
    const int bb = (lane & 15) * ROWB + ((lane >> 4) << 4);
    const int ra = lane >> 2;
    const int csh = (lane & 3) * 2;

    for (;;) {
        int tk;
        if (lane == 0) tk = (int)atomicAdd(&g_tickets[1], 1u);
        tk = __shfl_sync(0xffffffffu, tk, 0);
        if (tk >= ntiles) break;
        const int base = tk * 16;

#pragma unroll
        for (int i = 0; i < 16; i++) {
            int row = base + i; if (row >= N) row = N - 1;
            float4 v = *(const float4*)&g_acc[(size_t)row * H + lane * 4];
            st_h4(smc, OFF_A + (wr + i) * ROWB + lane * 8, v);
        }
        __syncwarp();

        float acc[16][4];
        zero16(acc);
        gemm16(smb + OFF_A, smb + OFF_W1B, acc, aa, bb);

        const int r0 = base + ra;
        const int r1 = r0 + 8;
        const bool v0 = r0 < N, v1 = r1 < N;
#pragma unroll
        for (int j = 0; j < 16; j++) {
            const float* c = acc[j];
            const int col = j * 8 + csh;
            float2 lo = { fmaxf(c[0], 0.f), fmaxf(c[1], 0.f) };
            float2 hi = { fmaxf(c[2], 0.f), fmaxf(c[3], 0.f) };
            if (v0) *(float2*)&node_out[(size_t)r0 * H + col] = lo;
            if (v1) *(float2*)&node_out[(size_t)r1 * H + col] = hi;
        }
        __syncwarp();
    }
}

// ---------------------------------------------------------------------------
extern "C" void kernel_launch(void* const* d_in, const int* in_sizes, int n_in,
                              void* d_out, int out_size) {
    const float* node = (const float*)d_in[0];
    const float* edge = (const float*)d_in[1];
    const int*   eidx = (const int*)d_in[2];
    const float* W1   = (const float*)d_in[3];
    const float* W2   = (const float*)d_in[4];
    const float* Wl   = (const float*)d_in[5];
    const float* e1   = (const float*)d_in[6];
    const float* e2   = (const float*)d_in[7];

    const int N = in_sizes[0] / H;
    const int E = in_sizes[1] / H;
    const int* src = eidx;
    const int* dst = eidx + E;

    float* out = (float*)d_out;
    float* node_out = out;                       // [N, H]
    float* edge_out = out + (size_t)N * H;       // [E, H]

    cudaFuncSetAttribute(k_edge_mma, cudaFuncAttributeMaxDynamicSharedMemorySize, SMEM_EDGE);
    cudaFuncSetAttribute(k_node_out, cudaFuncAttributeMaxDynamicSharedMemorySize, SMEM_1W);

    int nsm = 148;
    cudaDeviceGetAttribute(&nsm, cudaDevAttrMultiProcessorCount, 0);

    int tilesE = (E + 31) / 32;
    int tilesN = (N + 15) / 16;

    int preBlocks = (N * (H / 4) + NT - 1) / NT;
    k_node_pre<<<preBlocks, NT>>>(node, e1, N);
    k_edge_mma<<<nsm, NT, SMEM_EDGE>>>(edge, src, dst, W1, Wl, e2, edge_out, E, tilesE);
    k_node_out<<<nsm, NT, SMEM_1W>>>(W2, node_out, N, tilesN);
}